// round 13
// baseline (speedup 1.0000x reference)
#include <cuda_runtime.h>
#include <cuda_bf16.h>
#include <cuda_fp16.h>
#include <cstdint>

// ---------------------------------------------------------------------------
// GraphSAGE: out = normalize( [x | segsum(vals * x[cols])] @ W^T + b )
// N=100000, E=1600000, IN_F=OUT_F=128, rows sorted.
//
//   K1: prep — x -> fp16 + W fp16 image + row_start init.
//   K1b: rowidx — CSR row_start gap-fill from sorted rows.
//   K2: SpMM — warp-per-row, HALF-WARP per edge fp16 gather (1 LDG.128 = 2
//       edges, 2 wavefronts/edge), MLP2, fp32 accumulate, cross-half reduce,
//       fp16 store.
//   K3: fp16 HMMA GEMM, W resident in smem, A via cp.async double buffer,
//       2 CTAs/SM, fused bias + row L2-normalize.
// ---------------------------------------------------------------------------

#define NNODES   100000
#define INF      128
#define TWOK     256
#define OUTF     128

__device__ __half g_xh[(size_t)NNODES * INF];
__device__ __half g_nh[(size_t)NNODES * INF];
__device__ int    g_rowstart[NNODES + 1];
__device__ __align__(128) unsigned char g_Wh_img[65536];

// ---------------------------------------------------------------------------
// helpers
// ---------------------------------------------------------------------------
__device__ __forceinline__ uint32_t smem_u32(const void* p) {
    uint32_t a;
    asm("{ .reg .u64 t; cvta.to.shared.u64 t, %1; cvt.u32.u64 %0, t; }"
        : "=r"(a) : "l"(p));
    return a;
}
__device__ __forceinline__ uint32_t sw128(uint32_t off) {
    return off ^ ((off >> 3) & 0x70);
}
__device__ __forceinline__ void ldsm_x4(uint32_t& r0, uint32_t& r1,
                                        uint32_t& r2, uint32_t& r3, uint32_t a) {
    asm volatile("ldmatrix.sync.aligned.m8n8.x4.shared.b16 {%0,%1,%2,%3}, [%4];"
                 : "=r"(r0), "=r"(r1), "=r"(r2), "=r"(r3) : "r"(a));
}
__device__ __forceinline__ void mma_f16(float* c, const uint32_t* a,
                                        const uint32_t* b) {
    asm volatile(
        "mma.sync.aligned.m16n8k16.row.col.f32.f16.f16.f32 "
        "{%0,%1,%2,%3}, {%4,%5,%6,%7}, {%8,%9}, {%0,%1,%2,%3};"
        : "+f"(c[0]), "+f"(c[1]), "+f"(c[2]), "+f"(c[3])
        : "r"(a[0]), "r"(a[1]), "r"(a[2]), "r"(a[3]), "r"(b[0]), "r"(b[1]));
}
#define CP_ASYNC16(dst, src) \
    asm volatile("cp.async.cg.shared.global [%0], [%1], 16;" :: "r"(dst), "l"(src))
#define CP_ASYNC16Z(dst, src, sz) \
    asm volatile("cp.async.cg.shared.global [%0], [%1], 16, %2;" \
                 :: "r"(dst), "l"(src), "r"(sz))
#define CP_COMMIT() asm volatile("cp.async.commit_group;" ::: "memory")
#define CP_WAIT1()  asm volatile("cp.async.wait_group 1;" ::: "memory")
#define CP_WAIT0()  asm volatile("cp.async.wait_group 0;" ::: "memory")

// ---------------------------------------------------------------------------
// K1: x -> fp16 + W fp16 image + row_start init.
// ---------------------------------------------------------------------------
__global__ void prep_kernel(const float* __restrict__ x,
                            const float* __restrict__ W,
                            int nc8, int E, int N) {
    int i = blockIdx.x * blockDim.x + threadIdx.x;
    if (i < nc8) {
        float4 a = reinterpret_cast<const float4*>(x)[i * 2];
        float4 b = reinterpret_cast<const float4*>(x)[i * 2 + 1];
        __half2 h0 = __floats2half2_rn(a.x, a.y);
        __half2 h1 = __floats2half2_rn(a.z, a.w);
        __half2 h2 = __floats2half2_rn(b.x, b.y);
        __half2 h3 = __floats2half2_rn(b.z, b.w);
        uint4 o;
        o.x = *reinterpret_cast<uint32_t*>(&h0);
        o.y = *reinterpret_cast<uint32_t*>(&h1);
        o.z = *reinterpret_cast<uint32_t*>(&h2);
        o.w = *reinterpret_cast<uint32_t*>(&h3);
        reinterpret_cast<uint4*>(g_xh)[i] = o;
    }
    if (i <= N) g_rowstart[i] = E;
    if (i < 8192) {                     // W image: 8192 float4s
        int row   = i >> 6;
        int kf    = i & 63;
        int chunk = kf >> 4;
        int k4    = kf & 15;
        float4 wv = *reinterpret_cast<const float4*>(W + row * TWOK + chunk * 64 + k4 * 4);
        __half2 h0 = __floats2half2_rn(wv.x, wv.y);
        __half2 h1 = __floats2half2_rn(wv.z, wv.w);
        uint32_t off = chunk * 16384 + sw128((uint32_t)(row * 128 + k4 * 8));
        *reinterpret_cast<uint2*>(g_Wh_img + off) =
            make_uint2(*reinterpret_cast<uint32_t*>(&h0),
                       *reinterpret_cast<uint32_t*>(&h1));
    }
}

// ---------------------------------------------------------------------------
// K1b: CSR gap-fill from sorted rows.
// ---------------------------------------------------------------------------
__global__ void rowidx_kernel(const int* __restrict__ rows, int E) {
    int e = blockIdx.x * blockDim.x + threadIdx.x;
    if (e >= E) return;
    int r = __ldg(rows + e);
    int prev = (e == 0) ? -1 : __ldg(rows + e - 1);
    if (r != prev) {
        for (int q = prev + 1; q <= r; q++) g_rowstart[q] = e;
    }
}

// ---------------------------------------------------------------------------
// K2: SpMM, warp per row, half-warp per edge (fp16 gather).
//   lanes 0-15 handle even edges, 16-31 odd edges; lane covers dims
//   [8h, 8h+8), h = lane & 15. One LDG.128 serves two edges.
//   MLP2 (two pair-gathers in flight). Cross-half shfl.xor(16) reduce.
// ---------------------------------------------------------------------------
__global__ void spmm_kernel(const int*   __restrict__ cols,
                            const float* __restrict__ vals,
                            int N) {
    int warp = (blockIdx.x * blockDim.x + threadIdx.x) >> 5;
    int lane = threadIdx.x & 31;
    if (warp >= N) return;
    int row  = warp;
    int h    = lane & 15;        // dim group: dims [8h, 8h+8)
    int half = lane >> 4;        // 0 = even edge of pair, 1 = odd

    int s  = __ldg(g_rowstart + row);
    int en = __ldg(g_rowstart + row + 1);

    const uint4* xh4 = reinterpret_cast<const uint4*>(g_xh);   // 16 per row

    float a0[8], a1[8];
    #pragma unroll
    for (int i = 0; i < 8; i++) { a0[i] = 0.f; a1[i] = 0.f; }

    for (int e0 = s; e0 < en; e0 += 32) {
        int   idx = e0 + lane;
        bool  vd  = idx < en;
        int   c0  = vd ? __ldg(cols + idx) : 0;
        float v0  = vd ? __ldg(vals + idx) : 0.f;
        int n = min(32, en - e0);
        int j = 0;
        for (; j + 3 < n; j += 4) {
            int   ca = __shfl_sync(0xffffffffu, c0, j + half);
            float va = __shfl_sync(0xffffffffu, v0, j + half);
            int   cb = __shfl_sync(0xffffffffu, c0, j + 2 + half);
            float vb = __shfl_sync(0xffffffffu, v0, j + 2 + half);
            uint4 xa = xh4[(size_t)ca * 16 + h];
            uint4 xb = xh4[(size_t)cb * 16 + h];
            float2 p0 = __half22float2(*reinterpret_cast<__half2*>(&xa.x));
            float2 p1 = __half22float2(*reinterpret_cast<__half2*>(&xa.y));
            float2 p2 = __half22float2(*reinterpret_cast<__half2*>(&xa.z));
            float2 p3 = __half22float2(*reinterpret_cast<__half2*>(&xa.w));
            a0[0] = fmaf(va, p0.x, a0[0]); a0[1] = fmaf(va, p0.y, a0[1]);
            a0[2] = fmaf(va, p1.x, a0[2]); a0[3] = fmaf(va, p1.y, a0[3]);
            a0[4] = fmaf(va, p2.x, a0[4]); a0[5] = fmaf(va, p2.y, a0[5]);
            a0[6] = fmaf(va, p3.x, a0[6]); a0[7] = fmaf(va, p3.y, a0[7]);
            float2 q0 = __half22float2(*reinterpret_cast<__half2*>(&xb.x));
            float2 q1 = __half22float2(*reinterpret_cast<__half2*>(&xb.y));
            float2 q2 = __half22float2(*reinterpret_cast<__half2*>(&xb.z));
            float2 q3 = __half22float2(*reinterpret_cast<__half2*>(&xb.w));
            a1[0] = fmaf(vb, q0.x, a1[0]); a1[1] = fmaf(vb, q0.y, a1[1]);
            a1[2] = fmaf(vb, q1.x, a1[2]); a1[3] = fmaf(vb, q1.y, a1[3]);
            a1[4] = fmaf(vb, q2.x, a1[4]); a1[5] = fmaf(vb, q2.y, a1[5]);
            a1[6] = fmaf(vb, q3.x, a1[6]); a1[7] = fmaf(vb, q3.y, a1[7]);
        }
        for (; j < n; j += 2) {
            // half=1 with j+1 == n reads lane n: v0 there is 0 (padded), safe
            int   ca = __shfl_sync(0xffffffffu, c0, j + half);
            float va = __shfl_sync(0xffffffffu, v0, j + half);
            uint4 xa = xh4[(size_t)ca * 16 + h];
            float2 p0 = __half22float2(*reinterpret_cast<__half2*>(&xa.x));
            float2 p1 = __half22float2(*reinterpret_cast<__half2*>(&xa.y));
            float2 p2 = __half22float2(*reinterpret_cast<__half2*>(&xa.z));
            float2 p3 = __half22float2(*reinterpret_cast<__half2*>(&xa.w));
            a0[0] = fmaf(va, p0.x, a0[0]); a0[1] = fmaf(va, p0.y, a0[1]);
            a0[2] = fmaf(va, p1.x, a0[2]); a0[3] = fmaf(va, p1.y, a0[3]);
            a0[4] = fmaf(va, p2.x, a0[4]); a0[5] = fmaf(va, p2.y, a0[5]);
            a0[6] = fmaf(va, p3.x, a0[6]); a0[7] = fmaf(va, p3.y, a0[7]);
        }
    }

    // merge the two MLP accumulators, then combine even/odd halves
    #pragma unroll
    for (int i = 0; i < 8; i++) a0[i] += a1[i];
    #pragma unroll
    for (int i = 0; i < 8; i++)
        a0[i] += __shfl_xor_sync(0xffffffffu, a0[i], 16);

    if (half == 0) {
        __half2 h0 = __floats2half2_rn(a0[0], a0[1]);
        __half2 h1 = __floats2half2_rn(a0[2], a0[3]);
        __half2 h2 = __floats2half2_rn(a0[4], a0[5]);
        __half2 h3 = __floats2half2_rn(a0[6], a0[7]);
        uint4 o;
        o.x = *reinterpret_cast<uint32_t*>(&h0);
        o.y = *reinterpret_cast<uint32_t*>(&h1);
        o.z = *reinterpret_cast<uint32_t*>(&h2);
        o.w = *reinterpret_cast<uint32_t*>(&h3);
        reinterpret_cast<uint4*>(g_nh)[(size_t)row * 16 + h] = o;
    }
}

// ---------------------------------------------------------------------------
// K3: fp16 HMMA GEMM + bias + L2 normalize. (unchanged)
// ---------------------------------------------------------------------------
#define SM_W    0
#define SM_A    65536                 // 2 stages x 16384
#define SM_BIAS (SM_A + 32768)
#define SM_RSS  (SM_BIAS + 512)
#define SM_TOTAL (SM_RSS + 2048)

__global__ void __launch_bounds__(256, 2)
gemm_norm_kernel(const float* __restrict__ b,
                 float* __restrict__ out,
                 int N) {
    extern __shared__ char smem[];
    uint32_t sb = smem_u32(smem);
    float* bias = reinterpret_cast<float*>(smem + SM_BIAS);
    float (*rss)[128] = reinterpret_cast<float (*)[128]>(smem + SM_RSS);

    int t    = threadIdx.x;
    int wid  = t >> 5;
    int lane = t & 31;
    int warp_m = wid & 1;
    int warp_n = wid >> 1;
    int rowBase = blockIdx.x * 128;

    #pragma unroll
    for (int j = 0; j < 16; j++)
        CP_ASYNC16(sb + SM_W + t * 16 + j * 4096, g_Wh_img + t * 16 + j * 4096);

    const char* xb = reinterpret_cast<const char*>(g_xh);
    const char* nb = reinterpret_cast<const char*>(g_nh);

    auto stageA = [&](int c) {
        const char* srcb = (c < 2) ? (xb + c * 128) : (nb + (c - 2) * 128);
        uint32_t dstb = sb + SM_A + (c & 1) * 16384;
        #pragma unroll
        for (int j = 0; j < 4; j++) {
            int i  = t + 256 * j;
            int r  = i >> 3;
            int u8 = i & 7;
            int gr = rowBase + r;
            uint32_t sz = (gr < N) ? 16u : 0u;
            CP_ASYNC16Z(dstb + sw128((uint32_t)(r * 128 + u8 * 16)),
                        srcb + (size_t)gr * 256 + u8 * 16, sz);
        }
    };

    stageA(0); CP_COMMIT();
    stageA(1); CP_COMMIT();

    if (t < OUTF) bias[t] = __ldg(b + t);

    float acc[4][4][4];
    #pragma unroll
    for (int mi = 0; mi < 4; mi++)
        #pragma unroll
        for (int ni = 0; ni < 4; ni++)
            #pragma unroll
            for (int r = 0; r < 4; r++) acc[mi][ni][r] = 0.f;

    int aRow  = warp_m * 64 + (lane & 15);
    int aK8   = (lane >> 4) * 8;
    int bRowX = warp_n * 32 + (lane & 7) + ((lane >> 4) & 1) * 8;
    int bK8   = ((lane >> 3) & 1) * 8;

    #pragma unroll
    for (int c = 0; c < 4; c++) {
        if (c < 3) { CP_WAIT1(); } else { CP_WAIT0(); }
        __syncthreads();

        uint32_t aBuf  = sb + SM_A + (c & 1) * 16384;
        uint32_t wBase = sb + SM_W + c * 16384;
        #pragma unroll
        for (int kk = 0; kk < 64; kk += 16) {
            uint32_t a[4][4], bb[4][2];
            #pragma unroll
            for (int mi = 0; mi < 4; mi++) {
                uint32_t off = sw128((uint32_t)((aRow + mi * 16) * 128
                                                + (kk + aK8) * 2));
                ldsm_x4(a[mi][0], a[mi][1], a[mi][2], a[mi][3], aBuf + off);
            }
            #pragma unroll
            for (int p = 0; p < 2; p++) {
                uint32_t off = sw128((uint32_t)((bRowX + p * 16) * 128
                                                + (kk + bK8) * 2));
                ldsm_x4(bb[2*p][0], bb[2*p][1], bb[2*p+1][0], bb[2*p+1][1],
                        wBase + off);
            }
            #pragma unroll
            for (int mi = 0; mi < 4; mi++)
                #pragma unroll
                for (int ni = 0; ni < 4; ni++)
                    mma_f16(acc[mi][ni], a[mi], bb[ni]);
        }

        if (c < 2) {
            __syncthreads();
            stageA(c + 2); CP_COMMIT();
        }
    }

    // ---- epilogue ----
    int colBase = warp_n * 32 + 2 * (lane & 3);
    #pragma unroll
    for (int mi = 0; mi < 4; mi++)
        #pragma unroll
        for (int ni = 0; ni < 4; ni++) {
            float b0 = bias[colBase + ni * 8];
            float b1 = bias[colBase + ni * 8 + 1];
            acc[mi][ni][0] += b0;  acc[mi][ni][1] += b1;
            acc[mi][ni][2] += b0;  acc[mi][ni][3] += b1;
        }

    #pragma unroll
    for (int mi = 0; mi < 4; mi++) {
        #pragma unroll
        for (int half = 0; half < 2; half++) {
            float s = 0.f;
            #pragma unroll
            for (int ni = 0; ni < 4; ni++) {
                float c0 = acc[mi][ni][half * 2 + 0];
                float c1 = acc[mi][ni][half * 2 + 1];
                s = fmaf(c0, c0, s);
                s = fmaf(c1, c1, s);
            }
            s += __shfl_xor_sync(0xffffffffu, s, 1);
            s += __shfl_xor_sync(0xffffffffu, s, 2);
            if ((lane & 3) == 0)
                rss[warp_n][warp_m * 64 + mi * 16 + half * 8 + (lane >> 2)] = s;
        }
    }
    __syncthreads();

    float2* out2 = reinterpret_cast<float2*>(out);
    #pragma unroll
    for (int mi = 0; mi < 4; mi++) {
        #pragma unroll
        for (int half = 0; half < 2; half++) {
            int rl  = warp_m * 64 + mi * 16 + half * 8 + (lane >> 2);
            int row = rowBase + rl;
            if (row < N) {
                float ss = rss[0][rl] + rss[1][rl] + rss[2][rl] + rss[3][rl];
                float scale = 1.f / fmaxf(sqrtf(ss), 1e-12f);
                #pragma unroll
                for (int ni = 0; ni < 4; ni++) {
                    float2 o;
                    o.x = acc[mi][ni][half * 2 + 0] * scale;
                    o.y = acc[mi][ni][half * 2 + 1] * scale;
                    out2[(size_t)row * 64 + (colBase + ni * 8) / 2] = o;
                }
            }
        }
    }
}

// ---------------------------------------------------------------------------
// Launch
// ---------------------------------------------------------------------------
extern "C" void kernel_launch(void* const* d_in, const int* in_sizes, int n_in,
                              void* d_out, int out_size) {
    const float* x    = (const float*)d_in[0];
    const int*   rows = (const int*)  d_in[1];
    const int*   cols = (const int*)  d_in[2];
    const float* vals = (const float*)d_in[3];
    const float* W    = (const float*)d_in[4];
    const float* b    = (const float*)d_in[5];
    float*       out  = (float*)d_out;

    int N = in_sizes[0] / INF;
    int E = in_sizes[1];

    cudaFuncSetAttribute(gemm_norm_kernel,
                         cudaFuncAttributeMaxDynamicSharedMemorySize, SM_TOTAL);

    // K1: x fp16 + W image + row_start init
    int nc8 = N * (INF / 8);
    prep_kernel<<<(nc8 + 255) / 256, 256>>>(x, W, nc8, E, N);

    // K1b: CSR row_start gap-fill
    rowidx_kernel<<<(E + 255) / 256, 256>>>(rows, E);

    // K2: SpMM (warp per row, half-warp per edge, fp16 gather)
    int blocks = (N * 32 + 255) / 256;
    spmm_kernel<<<blocks, 256>>>(cols, vals, N);

    // K3: fp16 HMMA GEMM + bias + normalize
    gemm_norm_kernel<<<(N + 127) / 128, 256, SM_TOTAL>>>(b, out, N);
}

// round 14
// speedup vs baseline: 1.0670x; 1.0670x over previous
#include <cuda_runtime.h>
#include <cuda_bf16.h>
#include <cuda_fp16.h>
#include <cstdint>

// ---------------------------------------------------------------------------
// GraphSAGE: out = normalize( [x | segsum(vals * x[cols])] @ W^T + b )
// N=100000, E=1600000, IN_F=OUT_F=128, rows sorted.
//
//   K1: prep — row_start init + W fp16 image (tiny).
//   K1b: rowidx — CSR row_start gap-fill from sorted rows.
//   K2: SpMM — warp-per-row, fp32 gather, uniform-broadcast metadata LDG
//       (no SHFL), 2-way / MLP2, packed fma.rn.f32x2 (4 FFMA -> 2 FFMA2),
//       emits x -> fp16 and neighbor -> fp16.
//   K3: fp16 HMMA GEMM, W resident in smem, A via cp.async double buffer,
//       2 CTAs/SM, fused bias + row L2-normalize.
// ---------------------------------------------------------------------------

#define NNODES   100000
#define INF      128
#define TWOK     256
#define OUTF     128

__device__ __half g_xh[(size_t)NNODES * INF];
__device__ __half g_nh[(size_t)NNODES * INF];
__device__ int    g_rowstart[NNODES + 1];
__device__ __align__(128) unsigned char g_Wh_img[65536];

// ---------------------------------------------------------------------------
// helpers
// ---------------------------------------------------------------------------
__device__ __forceinline__ uint32_t smem_u32(const void* p) {
    uint32_t a;
    asm("{ .reg .u64 t; cvta.to.shared.u64 t, %1; cvt.u32.u64 %0, t; }"
        : "=r"(a) : "l"(p));
    return a;
}
__device__ __forceinline__ uint32_t sw128(uint32_t off) {
    return off ^ ((off >> 3) & 0x70);
}
__device__ __forceinline__ void ldsm_x4(uint32_t& r0, uint32_t& r1,
                                        uint32_t& r2, uint32_t& r3, uint32_t a) {
    asm volatile("ldmatrix.sync.aligned.m8n8.x4.shared.b16 {%0,%1,%2,%3}, [%4];"
                 : "=r"(r0), "=r"(r1), "=r"(r2), "=r"(r3) : "r"(a));
}
__device__ __forceinline__ void mma_f16(float* c, const uint32_t* a,
                                        const uint32_t* b) {
    asm volatile(
        "mma.sync.aligned.m16n8k16.row.col.f32.f16.f16.f32 "
        "{%0,%1,%2,%3}, {%4,%5,%6,%7}, {%8,%9}, {%0,%1,%2,%3};"
        : "+f"(c[0]), "+f"(c[1]), "+f"(c[2]), "+f"(c[3])
        : "r"(a[0]), "r"(a[1]), "r"(a[2]), "r"(a[3]), "r"(b[0]), "r"(b[1]));
}
__device__ __forceinline__ unsigned long long pack2(float lo, float hi) {
    unsigned long long r;
    asm("mov.b64 %0, {%1, %2};" : "=l"(r) : "f"(lo), "f"(hi));
    return r;
}
__device__ __forceinline__ float2 unpack2(unsigned long long v) {
    float2 f;
    asm("mov.b64 {%0, %1}, %2;" : "=f"(f.x), "=f"(f.y) : "l"(v));
    return f;
}
#define FMA2(d, a, b, c) \
    asm("fma.rn.f32x2 %0, %1, %2, %3;" : "=l"(d) : "l"(a), "l"(b), "l"(c))
#define CP_ASYNC16(dst, src) \
    asm volatile("cp.async.cg.shared.global [%0], [%1], 16;" :: "r"(dst), "l"(src))
#define CP_ASYNC16Z(dst, src, sz) \
    asm volatile("cp.async.cg.shared.global [%0], [%1], 16, %2;" \
                 :: "r"(dst), "l"(src), "r"(sz))
#define CP_COMMIT() asm volatile("cp.async.commit_group;" ::: "memory")
#define CP_WAIT1()  asm volatile("cp.async.wait_group 1;" ::: "memory")
#define CP_WAIT0()  asm volatile("cp.async.wait_group 0;" ::: "memory")

// ---------------------------------------------------------------------------
// K1: row_start init + W fp16 image (tiny).
// ---------------------------------------------------------------------------
__global__ void prep_kernel(const float* __restrict__ W, int E, int N) {
    int i = blockIdx.x * blockDim.x + threadIdx.x;
    if (i <= N) g_rowstart[i] = E;
    if (i < 8192) {                     // W image: 8192 float4s
        int row   = i >> 6;
        int kf    = i & 63;
        int chunk = kf >> 4;
        int k4    = kf & 15;
        float4 wv = *reinterpret_cast<const float4*>(W + row * TWOK + chunk * 64 + k4 * 4);
        __half2 h0 = __floats2half2_rn(wv.x, wv.y);
        __half2 h1 = __floats2half2_rn(wv.z, wv.w);
        uint32_t off = chunk * 16384 + sw128((uint32_t)(row * 128 + k4 * 8));
        *reinterpret_cast<uint2*>(g_Wh_img + off) =
            make_uint2(*reinterpret_cast<uint32_t*>(&h0),
                       *reinterpret_cast<uint32_t*>(&h1));
    }
}

// ---------------------------------------------------------------------------
// K1b: CSR gap-fill from sorted rows.
// ---------------------------------------------------------------------------
__global__ void rowidx_kernel(const int* __restrict__ rows, int E) {
    int e = blockIdx.x * blockDim.x + threadIdx.x;
    if (e >= E) return;
    int r = __ldg(rows + e);
    int prev = (e == 0) ? -1 : __ldg(rows + e - 1);
    if (r != prev) {
        for (int q = prev + 1; q <= r; q++) g_rowstart[q] = e;
    }
}

// ---------------------------------------------------------------------------
// K2: SpMM, warp per row. Lane owns dims [4l,4l+4).
// Uniform-broadcast metadata (__ldg of warp-uniform address), 2 edges per
// step with independent packed accumulators (MLP 2), fma.rn.f32x2.
// Emits neighbor fp16 AND the row's x as fp16 (for the GEMM).
// ---------------------------------------------------------------------------
__global__ void spmm_kernel(const float* __restrict__ x,
                            const int*   __restrict__ cols,
                            const float* __restrict__ vals,
                            int N) {
    int warp = (blockIdx.x * blockDim.x + threadIdx.x) >> 5;
    int lane = threadIdx.x & 31;
    if (warp >= N) return;
    int row = warp;

    int s  = __ldg(g_rowstart + row);
    int en = __ldg(g_rowstart + row + 1);

    const float4* x4 = reinterpret_cast<const float4*>(x);

    unsigned long long A0 = 0, A1 = 0, B0 = 0, B1 = 0;

    int e = s;
    for (; e + 1 < en; e += 2) {
        int   c0 = __ldg(cols + e);
        int   c1 = __ldg(cols + e + 1);
        float v0 = __ldg(vals + e);
        float v1 = __ldg(vals + e + 1);
        float4 xa = x4[(size_t)c0 * 32 + lane];
        float4 xb = x4[(size_t)c1 * 32 + lane];
        unsigned long long va = pack2(v0, v0);
        unsigned long long vb = pack2(v1, v1);
        FMA2(A0, pack2(xa.x, xa.y), va, A0);
        FMA2(A1, pack2(xa.z, xa.w), va, A1);
        FMA2(B0, pack2(xb.x, xb.y), vb, B0);
        FMA2(B1, pack2(xb.z, xb.w), vb, B1);
    }
    if (e < en) {
        int   c0 = __ldg(cols + e);
        float v0 = __ldg(vals + e);
        float4 xa = x4[(size_t)c0 * 32 + lane];
        unsigned long long va = pack2(v0, v0);
        FMA2(A0, pack2(xa.x, xa.y), va, A0);
        FMA2(A1, pack2(xa.z, xa.w), va, A1);
    }

    float2 r0 = unpack2(A0), r1 = unpack2(A1);
    float2 s0 = unpack2(B0), s1 = unpack2(B1);
    float o0 = r0.x + s0.x, o1 = r0.y + s0.y;
    float o2 = r1.x + s1.x, o3 = r1.y + s1.y;

    __half2 h0 = __floats2half2_rn(o0, o1);
    __half2 h1 = __floats2half2_rn(o2, o3);
    reinterpret_cast<uint2*>(g_nh)[(size_t)row * 32 + lane] =
        make_uint2(*reinterpret_cast<uint32_t*>(&h0),
                   *reinterpret_cast<uint32_t*>(&h1));

    // x row -> fp16 (feeds GEMM chunks 0-1)
    float4 xr = x4[(size_t)row * 32 + lane];
    __half2 g0 = __floats2half2_rn(xr.x, xr.y);
    __half2 g1 = __floats2half2_rn(xr.z, xr.w);
    reinterpret_cast<uint2*>(g_xh)[(size_t)row * 32 + lane] =
        make_uint2(*reinterpret_cast<uint32_t*>(&g0),
                   *reinterpret_cast<uint32_t*>(&g1));
}

// ---------------------------------------------------------------------------
// K3: fp16 HMMA GEMM + bias + L2 normalize. (unchanged)
// ---------------------------------------------------------------------------
#define SM_W    0
#define SM_A    65536                 // 2 stages x 16384
#define SM_BIAS (SM_A + 32768)
#define SM_RSS  (SM_BIAS + 512)
#define SM_TOTAL (SM_RSS + 2048)

__global__ void __launch_bounds__(256, 2)
gemm_norm_kernel(const float* __restrict__ b,
                 float* __restrict__ out,
                 int N) {
    extern __shared__ char smem[];
    uint32_t sb = smem_u32(smem);
    float* bias = reinterpret_cast<float*>(smem + SM_BIAS);
    float (*rss)[128] = reinterpret_cast<float (*)[128]>(smem + SM_RSS);

    int t    = threadIdx.x;
    int wid  = t >> 5;
    int lane = t & 31;
    int warp_m = wid & 1;
    int warp_n = wid >> 1;
    int rowBase = blockIdx.x * 128;

    #pragma unroll
    for (int j = 0; j < 16; j++)
        CP_ASYNC16(sb + SM_W + t * 16 + j * 4096, g_Wh_img + t * 16 + j * 4096);

    const char* xb = reinterpret_cast<const char*>(g_xh);
    const char* nb = reinterpret_cast<const char*>(g_nh);

    auto stageA = [&](int c) {
        const char* srcb = (c < 2) ? (xb + c * 128) : (nb + (c - 2) * 128);
        uint32_t dstb = sb + SM_A + (c & 1) * 16384;
        #pragma unroll
        for (int j = 0; j < 4; j++) {
            int i  = t + 256 * j;
            int r  = i >> 3;
            int u8 = i & 7;
            int gr = rowBase + r;
            uint32_t sz = (gr < N) ? 16u : 0u;
            CP_ASYNC16Z(dstb + sw128((uint32_t)(r * 128 + u8 * 16)),
                        srcb + (size_t)gr * 256 + u8 * 16, sz);
        }
    };

    stageA(0); CP_COMMIT();
    stageA(1); CP_COMMIT();

    if (t < OUTF) bias[t] = __ldg(b + t);

    float acc[4][4][4];
    #pragma unroll
    for (int mi = 0; mi < 4; mi++)
        #pragma unroll
        for (int ni = 0; ni < 4; ni++)
            #pragma unroll
            for (int r = 0; r < 4; r++) acc[mi][ni][r] = 0.f;

    int aRow  = warp_m * 64 + (lane & 15);
    int aK8   = (lane >> 4) * 8;
    int bRowX = warp_n * 32 + (lane & 7) + ((lane >> 4) & 1) * 8;
    int bK8   = ((lane >> 3) & 1) * 8;

    #pragma unroll
    for (int c = 0; c < 4; c++) {
        if (c < 3) { CP_WAIT1(); } else { CP_WAIT0(); }
        __syncthreads();

        uint32_t aBuf  = sb + SM_A + (c & 1) * 16384;
        uint32_t wBase = sb + SM_W + c * 16384;
        #pragma unroll
        for (int kk = 0; kk < 64; kk += 16) {
            uint32_t a[4][4], bb[4][2];
            #pragma unroll
            for (int mi = 0; mi < 4; mi++) {
                uint32_t off = sw128((uint32_t)((aRow + mi * 16) * 128
                                                + (kk + aK8) * 2));
                ldsm_x4(a[mi][0], a[mi][1], a[mi][2], a[mi][3], aBuf + off);
            }
            #pragma unroll
            for (int p = 0; p < 2; p++) {
                uint32_t off = sw128((uint32_t)((bRowX + p * 16) * 128
                                                + (kk + bK8) * 2));
                ldsm_x4(bb[2*p][0], bb[2*p][1], bb[2*p+1][0], bb[2*p+1][1],
                        wBase + off);
            }
            #pragma unroll
            for (int mi = 0; mi < 4; mi++)
                #pragma unroll
                for (int ni = 0; ni < 4; ni++)
                    mma_f16(acc[mi][ni], a[mi], bb[ni]);
        }

        if (c < 2) {
            __syncthreads();
            stageA(c + 2); CP_COMMIT();
        }
    }

    // ---- epilogue ----
    int colBase = warp_n * 32 + 2 * (lane & 3);
    #pragma unroll
    for (int mi = 0; mi < 4; mi++)
        #pragma unroll
        for (int ni = 0; ni < 4; ni++) {
            float b0 = bias[colBase + ni * 8];
            float b1 = bias[colBase + ni * 8 + 1];
            acc[mi][ni][0] += b0;  acc[mi][ni][1] += b1;
            acc[mi][ni][2] += b0;  acc[mi][ni][3] += b1;
        }

    #pragma unroll
    for (int mi = 0; mi < 4; mi++) {
        #pragma unroll
        for (int half = 0; half < 2; half++) {
            float s = 0.f;
            #pragma unroll
            for (int ni = 0; ni < 4; ni++) {
                float c0 = acc[mi][ni][half * 2 + 0];
                float c1 = acc[mi][ni][half * 2 + 1];
                s = fmaf(c0, c0, s);
                s = fmaf(c1, c1, s);
            }
            s += __shfl_xor_sync(0xffffffffu, s, 1);
            s += __shfl_xor_sync(0xffffffffu, s, 2);
            if ((lane & 3) == 0)
                rss[warp_n][warp_m * 64 + mi * 16 + half * 8 + (lane >> 2)] = s;
        }
    }
    __syncthreads();

    float2* out2 = reinterpret_cast<float2*>(out);
    #pragma unroll
    for (int mi = 0; mi < 4; mi++) {
        #pragma unroll
        for (int half = 0; half < 2; half++) {
            int rl  = warp_m * 64 + mi * 16 + half * 8 + (lane >> 2);
            int row = rowBase + rl;
            if (row < N) {
                float ss = rss[0][rl] + rss[1][rl] + rss[2][rl] + rss[3][rl];
                float scale = 1.f / fmaxf(sqrtf(ss), 1e-12f);
                #pragma unroll
                for (int ni = 0; ni < 4; ni++) {
                    float2 o;
                    o.x = acc[mi][ni][half * 2 + 0] * scale;
                    o.y = acc[mi][ni][half * 2 + 1] * scale;
                    out2[(size_t)row * 64 + (colBase + ni * 8) / 2] = o;
                }
            }
        }
    }
}

// ---------------------------------------------------------------------------
// Launch
// ---------------------------------------------------------------------------
extern "C" void kernel_launch(void* const* d_in, const int* in_sizes, int n_in,
                              void* d_out, int out_size) {
    const float* x    = (const float*)d_in[0];
    const int*   rows = (const int*)  d_in[1];
    const int*   cols = (const int*)  d_in[2];
    const float* vals = (const float*)d_in[3];
    const float* W    = (const float*)d_in[4];
    const float* b    = (const float*)d_in[5];
    float*       out  = (float*)d_out;

    int N = in_sizes[0] / INF;
    int E = in_sizes[1];

    cudaFuncSetAttribute(gemm_norm_kernel,
                         cudaFuncAttributeMaxDynamicSharedMemorySize, SM_TOTAL);

    // K1: row_start init + W image (tiny)
    prep_kernel<<<(N + 256) / 256, 256>>>(W, E, N);

    // K1b: CSR row_start gap-fill
    rowidx_kernel<<<(E + 255) / 256, 256>>>(rows, E);

    // K2: SpMM (warp per row, uniform metadata, FFMA2, MLP2; emits x fp16)
    int blocks = (N * 32 + 255) / 256;
    spmm_kernel<<<blocks, 256>>>(x, cols, vals, N);

    // K3: fp16 HMMA GEMM + bias + normalize
    gemm_norm_kernel<<<(N + 127) / 128, 256, SM_TOTAL>>>(b, out, N);
}